// round 1
// baseline (speedup 1.0000x reference)
#include <cuda_runtime.h>
#include <cstdint>
#include <cstddef>

#define T_TOK 1568
#define DMODEL 768
#define HDIM   64
#define NEXP   8
#define FFDIM  3072
#define LN_EPS 1e-5f

#define BM 64
#define BN 64
#define BK 32
#define PADA 67
#define PADB 68
#define MTILES ((T_TOK + BM - 1) / BM)   // 25

// ---------------- static scratch (no dynamic allocation allowed) ----------------
__device__ float g_h2[(size_t)T_TOK * DMODEL];
__device__ float g_mid[(size_t)T_TOK * FFDIM];
__device__ int   g_top1[T_TOK];
__device__ int   g_perm[T_TOK];
__device__ int   g_off[NEXP + 1];

// ---------------- helpers ----------------
__device__ __forceinline__ float gelu_f(float v) {
    // exact (erf-based) gelu, matching jax.nn.gelu(approximate=False)
    return 0.5f * v * (1.0f + erff(v * 0.70710678118654752440f));
}

__device__ __forceinline__ uint32_t f2tf(float f) {
    uint32_t u;
    asm("cvt.rna.tf32.f32 %0, %1;" : "=r"(u) : "f"(f));
    return u;
}

__device__ __forceinline__ void mma_tf32(float c[4], const uint32_t a[4], const uint32_t b[2]) {
    asm volatile(
        "mma.sync.aligned.m16n8k8.row.col.f32.tf32.tf32.f32 "
        "{%0,%1,%2,%3},{%4,%5,%6,%7},{%8,%9},{%0,%1,%2,%3};\n"
        : "+f"(c[0]), "+f"(c[1]), "+f"(c[2]), "+f"(c[3])
        : "r"(a[0]), "r"(a[1]), "r"(a[2]), "r"(a[3]), "r"(b[0]), "r"(b[1]));
}

// ---------------- K1: LN1 + v GEMV + residual + LN2 + gating/argmax ----------------
// Math: attention output per head == v (k,v broadcast over heads -> uniform softmax),
// so x1[d] = x[d] + v[d & 63].  softmax(gates) is monotone -> argmax of raw logits.
__global__ __launch_bounds__(256) void k_pre(
    const float* __restrict__ x,
    const float* __restrict__ ln1g, const float* __restrict__ ln1b,
    const float* __restrict__ Wv,   const float* __restrict__ bv,
    const float* __restrict__ ln2g, const float* __restrict__ ln2b,
    const float* __restrict__ Wg,   const float* __restrict__ bg,
    float* __restrict__ out)
{
    const int t = blockIdx.x;
    const int tid = threadIdx.x;

    __shared__ float sx[DMODEL];
    __shared__ float sh[DMODEL];
    __shared__ float sv[HDIM];
    __shared__ float slog[NEXP];
    __shared__ float2 red2[256];

    const float* xr = x + (size_t)t * DMODEL;
    float l0 = xr[tid], l1 = xr[tid + 256], l2 = xr[tid + 512];
    sx[tid] = l0; sx[tid + 256] = l1; sx[tid + 512] = l2;

    // ---- LN1 stats ----
    red2[tid] = make_float2(l0 + l1 + l2, l0 * l0 + l1 * l1 + l2 * l2);
    __syncthreads();
    for (int o = 128; o > 0; o >>= 1) {
        if (tid < o) {
            red2[tid].x += red2[tid + o].x;
            red2[tid].y += red2[tid + o].y;
        }
        __syncthreads();
    }
    float mean = red2[0].x * (1.0f / DMODEL);
    float var  = red2[0].y * (1.0f / DMODEL) - mean * mean;
    float rstd = rsqrtf(var + LN_EPS);

    #pragma unroll
    for (int i = 0; i < 3; i++) {
        int d = tid + i * 256;
        sh[d] = (sx[d] - mean) * rstd * ln1g[d] + ln1b[d];
    }
    __syncthreads();

    // ---- v = LN1(x) @ Wv + bv  (768 x 64 GEMV) ----
    {
        int j = tid & 63, part = tid >> 6;   // 4 K-parts of 192
        float acc = 0.0f;
        int kbeg = part * 192;
        #pragma unroll 8
        for (int k = kbeg; k < kbeg + 192; ++k) acc += sh[k] * Wv[k * HDIM + j];
        red2[tid].x = acc;
        __syncthreads();
        if (tid < 64)
            sv[tid] = red2[tid].x + red2[tid + 64].x + red2[tid + 128].x + red2[tid + 192].x + bv[tid];
        __syncthreads();
    }

    // ---- x1 = x + tile(v)  -> residual written to out; LN2 stats ----
    float xs = 0.0f, xsq = 0.0f;
    #pragma unroll
    for (int i = 0; i < 3; i++) {
        int d = tid + i * 256;
        float v1 = sx[d] + sv[d & 63];
        out[(size_t)t * DMODEL + d] = v1;
        sx[d] = v1;
        xs += v1; xsq += v1 * v1;
    }
    __syncthreads();
    red2[tid] = make_float2(xs, xsq);
    __syncthreads();
    for (int o = 128; o > 0; o >>= 1) {
        if (tid < o) {
            red2[tid].x += red2[tid + o].x;
            red2[tid].y += red2[tid + o].y;
        }
        __syncthreads();
    }
    float mean2 = red2[0].x * (1.0f / DMODEL);
    float var2  = red2[0].y * (1.0f / DMODEL) - mean2 * mean2;
    float rstd2 = rsqrtf(var2 + LN_EPS);

    #pragma unroll
    for (int i = 0; i < 3; i++) {
        int d = tid + i * 256;
        float h2 = (sx[d] - mean2) * rstd2 * ln2g[d] + ln2b[d];
        g_h2[(size_t)t * DMODEL + d] = h2;
        sh[d] = h2;
    }
    __syncthreads();

    // ---- gating logits + argmax (softmax monotone) ----
    {
        int je = tid & 7, pe = tid >> 3;   // 32 K-parts of 24
        float acc = 0.0f;
        int kbeg = pe * 24;
        #pragma unroll
        for (int k = kbeg; k < kbeg + 24; ++k) acc += sh[k] * Wg[k * NEXP + je];
        red2[tid].x = acc;
        __syncthreads();
        if (tid < NEXP) {
            float lsum = bg[tid];
            #pragma unroll
            for (int p = 0; p < 32; ++p) lsum += red2[p * 8 + tid].x;
            slog[tid] = lsum;
        }
        __syncthreads();
        if (tid == 0) {
            int best = 0;
            float bvl = slog[0];
            #pragma unroll
            for (int e = 1; e < NEXP; ++e)
                if (slog[e] > bvl) { bvl = slog[e]; best = e; }   // first-max == jnp.argmax
            g_top1[t] = best;
        }
    }
}

// ---------------- K2: route/compact tokens by expert ----------------
__global__ __launch_bounds__(512) void k_route()
{
    __shared__ int cnt[NEXP];
    __shared__ int base[NEXP];
    int tid = threadIdx.x;
    if (tid < NEXP) cnt[tid] = 0;
    __syncthreads();
    for (int t = tid; t < T_TOK; t += 512) atomicAdd(&cnt[g_top1[t]], 1);
    __syncthreads();
    if (tid == 0) {
        int s = 0;
        for (int e = 0; e < NEXP; ++e) { base[e] = s; g_off[e] = s; s += cnt[e]; }
        g_off[NEXP] = s;
    }
    __syncthreads();
    if (tid < NEXP) cnt[tid] = 0;   // reuse as cursor
    __syncthreads();
    for (int t = tid; t < T_TOK; t += 512) {
        int e = g_top1[t];
        int pos = base[e] + atomicAdd(&cnt[e], 1);
        g_perm[pos] = t;
    }
}

// ---------------- K3: mid = gelu(h2[perm] @ W1[e] + b1[e])  (tf32 mma) ----------------
__global__ __launch_bounds__(128) void k_ffn1(
    const float* __restrict__ W1, const float* __restrict__ b1)
{
    const int e  = blockIdx.z;
    const int off = g_off[e];
    const int Me  = g_off[e + 1] - off;
    const int m0  = blockIdx.y * BM;
    if (m0 >= Me) return;
    const int n0  = blockIdx.x * BN;

    __shared__ uint32_t As[BK * PADA];
    __shared__ uint32_t Bs[BK * PADB];

    const int tid  = threadIdx.x;
    const int lane = tid & 31, wid = tid >> 5;
    const int wm = (wid >> 1) * 32, wn = (wid & 1) * 32;
    const int grp = lane >> 2, tg = lane & 3;

    float C[2][4][4];
    #pragma unroll
    for (int i = 0; i < 2; i++)
        #pragma unroll
        for (int j = 0; j < 4; j++)
            #pragma unroll
            for (int q = 0; q < 4; q++) C[i][j][q] = 0.0f;

    // A gather setup: thread -> (row ar, half ah of 16 K-cols)
    const int ar = tid >> 1, ah = tid & 1;
    const bool avalid = (m0 + ar) < Me;
    const int tok = avalid ? g_perm[off + m0 + ar] : 0;
    const float* Arow = g_h2 + (size_t)tok * DMODEL;

    const float* Wb = W1 + (size_t)e * DMODEL * FFDIM;
    const int br = tid >> 4, bc = tid & 15;

    for (int k0 = 0; k0 < DMODEL; k0 += BK) {
        // stage A (transposed, tf32)
        #pragma unroll
        for (int v = 0; v < 4; v++) {
            float4 f = avalid ? *(const float4*)(Arow + k0 + ah * 16 + v * 4)
                              : make_float4(0.f, 0.f, 0.f, 0.f);
            int kk = ah * 16 + v * 4;
            As[(kk + 0) * PADA + ar] = f2tf(f.x);
            As[(kk + 1) * PADA + ar] = f2tf(f.y);
            As[(kk + 2) * PADA + ar] = f2tf(f.z);
            As[(kk + 3) * PADA + ar] = f2tf(f.w);
        }
        // stage B (k-major rows, tf32)
        #pragma unroll
        for (int it = 0; it < 4; it++) {
            int kr = br + it * 8;
            float4 f = *(const float4*)(Wb + (size_t)(k0 + kr) * FFDIM + n0 + bc * 4);
            uint32_t* bp = &Bs[kr * PADB + bc * 4];
            bp[0] = f2tf(f.x); bp[1] = f2tf(f.y); bp[2] = f2tf(f.z); bp[3] = f2tf(f.w);
        }
        __syncthreads();

        #pragma unroll
        for (int ks = 0; ks < 4; ks++) {
            const int kb = ks * 8;
            uint32_t a[2][4], b[4][2];
            #pragma unroll
            for (int i = 0; i < 2; i++) {
                int r = wm + i * 16 + grp;
                a[i][0] = As[(kb + tg) * PADA + r];
                a[i][1] = As[(kb + tg) * PADA + r + 8];
                a[i][2] = As[(kb + tg + 4) * PADA + r];
                a[i][3] = As[(kb + tg + 4) * PADA + r + 8];
            }
            #pragma unroll
            for (int j = 0; j < 4; j++) {
                int n = wn + j * 8 + grp;
                b[j][0] = Bs[(kb + tg) * PADB + n];
                b[j][1] = Bs[(kb + tg + 4) * PADB + n];
            }
            #pragma unroll
            for (int i = 0; i < 2; i++)
                #pragma unroll
                for (int j = 0; j < 4; j++)
                    mma_tf32(C[i][j], a[i], b[j]);
        }
        __syncthreads();
    }

    // epilogue: +b1, gelu, store mid (compacted rows)
    const float* bb = b1 + (size_t)e * FFDIM + n0;
    #pragma unroll
    for (int i = 0; i < 2; i++) {
        int r_lo = wm + i * 16 + grp;
        int r_hi = r_lo + 8;
        #pragma unroll
        for (int j = 0; j < 4; j++) {
            int nc = wn + j * 8 + tg * 2;
            if (m0 + r_lo < Me) {
                size_t base = (size_t)(off + m0 + r_lo) * FFDIM + n0 + nc;
                g_mid[base]     = gelu_f(C[i][j][0] + bb[nc]);
                g_mid[base + 1] = gelu_f(C[i][j][1] + bb[nc + 1]);
            }
            if (m0 + r_hi < Me) {
                size_t base = (size_t)(off + m0 + r_hi) * FFDIM + n0 + nc;
                g_mid[base]     = gelu_f(C[i][j][2] + bb[nc]);
                g_mid[base + 1] = gelu_f(C[i][j][3] + bb[nc + 1]);
            }
        }
    }
}

// ---------------- K4: out[perm] += mid @ W2[e] + b2[e]  (tf32 mma) ----------------
__global__ __launch_bounds__(128) void k_ffn2(
    const float* __restrict__ W2, const float* __restrict__ b2,
    float* __restrict__ out)
{
    const int e  = blockIdx.z;
    const int off = g_off[e];
    const int Me  = g_off[e + 1] - off;
    const int m0  = blockIdx.y * BM;
    if (m0 >= Me) return;
    const int n0  = blockIdx.x * BN;

    __shared__ uint32_t As[BK * PADA];
    __shared__ uint32_t Bs[BK * PADB];

    const int tid  = threadIdx.x;
    const int lane = tid & 31, wid = tid >> 5;
    const int wm = (wid >> 1) * 32, wn = (wid & 1) * 32;
    const int grp = lane >> 2, tg = lane & 3;

    float C[2][4][4];
    #pragma unroll
    for (int i = 0; i < 2; i++)
        #pragma unroll
        for (int j = 0; j < 4; j++)
            #pragma unroll
            for (int q = 0; q < 4; q++) C[i][j][q] = 0.0f;

    const int ar = tid >> 1, ah = tid & 1;
    const bool avalid = (m0 + ar) < Me;
    const float* Arow = g_mid + (size_t)(off + m0 + ar) * FFDIM;

    const float* Wb = W2 + (size_t)e * FFDIM * DMODEL;
    const int br = tid >> 4, bc = tid & 15;

    for (int k0 = 0; k0 < FFDIM; k0 += BK) {
        #pragma unroll
        for (int v = 0; v < 4; v++) {
            float4 f = avalid ? *(const float4*)(Arow + k0 + ah * 16 + v * 4)
                              : make_float4(0.f, 0.f, 0.f, 0.f);
            int kk = ah * 16 + v * 4;
            As[(kk + 0) * PADA + ar] = f2tf(f.x);
            As[(kk + 1) * PADA + ar] = f2tf(f.y);
            As[(kk + 2) * PADA + ar] = f2tf(f.z);
            As[(kk + 3) * PADA + ar] = f2tf(f.w);
        }
        #pragma unroll
        for (int it = 0; it < 4; it++) {
            int kr = br + it * 8;
            float4 f = *(const float4*)(Wb + (size_t)(k0 + kr) * DMODEL + n0 + bc * 4);
            uint32_t* bp = &Bs[kr * PADB + bc * 4];
            bp[0] = f2tf(f.x); bp[1] = f2tf(f.y); bp[2] = f2tf(f.z); bp[3] = f2tf(f.w);
        }
        __syncthreads();

        #pragma unroll
        for (int ks = 0; ks < 4; ks++) {
            const int kb = ks * 8;
            uint32_t a[2][4], b[4][2];
            #pragma unroll
            for (int i = 0; i < 2; i++) {
                int r = wm + i * 16 + grp;
                a[i][0] = As[(kb + tg) * PADA + r];
                a[i][1] = As[(kb + tg) * PADA + r + 8];
                a[i][2] = As[(kb + tg + 4) * PADA + r];
                a[i][3] = As[(kb + tg + 4) * PADA + r + 8];
            }
            #pragma unroll
            for (int j = 0; j < 4; j++) {
                int n = wn + j * 8 + grp;
                b[j][0] = Bs[(kb + tg) * PADB + n];
                b[j][1] = Bs[(kb + tg + 4) * PADB + n];
            }
            #pragma unroll
            for (int i = 0; i < 2; i++)
                #pragma unroll
                for (int j = 0; j < 4; j++)
                    mma_tf32(C[i][j], a[i], b[j]);
        }
        __syncthreads();
    }

    // epilogue: +b2, scatter-add into residual out[token]
    const float* bb = b2 + (size_t)e * DMODEL + n0;
    #pragma unroll
    for (int i = 0; i < 2; i++) {
        int r_lo = wm + i * 16 + grp;
        int r_hi = r_lo + 8;
        #pragma unroll
        for (int j = 0; j < 4; j++) {
            int nc = wn + j * 8 + tg * 2;
            if (m0 + r_lo < Me) {
                int tok = g_perm[off + m0 + r_lo];
                float* o = out + (size_t)tok * DMODEL + n0 + nc;
                o[0] += C[i][j][0] + bb[nc];
                o[1] += C[i][j][1] + bb[nc + 1];
            }
            if (m0 + r_hi < Me) {
                int tok = g_perm[off + m0 + r_hi];
                float* o = out + (size_t)tok * DMODEL + n0 + nc;
                o[0] += C[i][j][2] + bb[nc];
                o[1] += C[i][j][3] + bb[nc + 1];
            }
        }
    }
}

// ---------------- launch ----------------
extern "C" void kernel_launch(void* const* d_in, const int* in_sizes, int n_in,
                              void* d_out, int out_size)
{
    (void)in_sizes; (void)n_in; (void)out_size;
    const float* x    = (const float*)d_in[0];
    const float* ln1g = (const float*)d_in[1];
    const float* ln1b = (const float*)d_in[2];
    // d_in[3..6] = Wq,bq,Wk,bk : analytically cancelled (uniform softmax over heads)
    const float* Wv   = (const float*)d_in[7];
    const float* bv   = (const float*)d_in[8];
    const float* ln2g = (const float*)d_in[9];
    const float* ln2b = (const float*)d_in[10];
    const float* Wg   = (const float*)d_in[11];
    const float* bg   = (const float*)d_in[12];
    const float* W1   = (const float*)d_in[13];
    const float* b1   = (const float*)d_in[14];
    const float* W2   = (const float*)d_in[15];
    const float* b2   = (const float*)d_in[16];
    float* out = (float*)d_out;

    k_pre<<<T_TOK, 256>>>(x, ln1g, ln1b, Wv, bv, ln2g, ln2b, Wg, bg, out);
    k_route<<<1, 512>>>();
    k_ffn1<<<dim3(FFDIM / BN, MTILES, NEXP), 128>>>(W1, b1);
    k_ffn2<<<dim3(DMODEL / BN, MTILES, NEXP), 128>>>(W2, b2, out);
}

// round 2
// speedup vs baseline: 1.9819x; 1.9819x over previous
#include <cuda_runtime.h>
#include <cstdint>
#include <cstddef>

#define T_TOK 1568
#define DMODEL 768
#define HDIM   64
#define NEXP   8
#define FFDIM  3072
#define LN_EPS 1e-5f

// GEMM tiling
#define BM 128
#define BN 64
#define BK 32
#define PADA 136   // As row stride (elems), 136 % 32 == 8 -> conflict-free frags
#define PADB 72    // Bs row stride (elems), 72 % 32 == 8
#define A_ELEMS (BK * PADA)
#define B_ELEMS (BK * PADB)
#define SMEM_BYTES ((A_ELEMS + B_ELEMS) * 2 * 4)
#define MT128 ((T_TOK + BM - 1) / BM)   // 13
#define NSPLIT 4                         // split-K for ffn2

// ---------------- static scratch ----------------
__device__ float g_h2[(size_t)T_TOK * DMODEL];
__device__ float g_mid[(size_t)T_TOK * FFDIM];
__device__ int   g_top1[T_TOK];
__device__ int   g_perm[T_TOK];
__device__ int   g_off[NEXP + 1];

// ---------------- helpers ----------------
__device__ __forceinline__ float gelu_f(float v) {
    return 0.5f * v * (1.0f + erff(v * 0.70710678118654752440f));
}

__device__ __forceinline__ uint32_t f2tf(float f) {
    uint32_t u;
    asm("cvt.rna.tf32.f32 %0, %1;" : "=r"(u) : "f"(f));
    return u;
}

__device__ __forceinline__ void mma_tf32(float c[4], const uint32_t a[4], const uint32_t b[2]) {
    asm volatile(
        "mma.sync.aligned.m16n8k8.row.col.f32.tf32.tf32.f32 "
        "{%0,%1,%2,%3},{%4,%5,%6,%7},{%8,%9},{%0,%1,%2,%3};\n"
        : "+f"(c[0]), "+f"(c[1]), "+f"(c[2]), "+f"(c[3])
        : "r"(a[0]), "r"(a[1]), "r"(a[2]), "r"(a[3]), "r"(b[0]), "r"(b[1]));
}

// ---------------- K1: LN1 + v GEMV + residual + LN2 + gating/argmax ----------------
// attention out == v exactly (k,v broadcast over heads -> uniform softmax);
// gating softmax is monotone -> argmax of raw logits.
__global__ __launch_bounds__(256) void k_pre(
    const float* __restrict__ x,
    const float* __restrict__ ln1g, const float* __restrict__ ln1b,
    const float* __restrict__ Wv,   const float* __restrict__ bv,
    const float* __restrict__ ln2g, const float* __restrict__ ln2b,
    const float* __restrict__ Wg,   const float* __restrict__ bg,
    float* __restrict__ out)
{
    const int t = blockIdx.x;
    const int tid = threadIdx.x;

    __shared__ float sx[DMODEL];
    __shared__ float sh[DMODEL];
    __shared__ float sv[HDIM];
    __shared__ float slog[NEXP];
    __shared__ float2 red2[256];

    const float* xr = x + (size_t)t * DMODEL;
    float l0 = xr[tid], l1 = xr[tid + 256], l2 = xr[tid + 512];
    sx[tid] = l0; sx[tid + 256] = l1; sx[tid + 512] = l2;

    red2[tid] = make_float2(l0 + l1 + l2, l0 * l0 + l1 * l1 + l2 * l2);
    __syncthreads();
    for (int o = 128; o > 0; o >>= 1) {
        if (tid < o) {
            red2[tid].x += red2[tid + o].x;
            red2[tid].y += red2[tid + o].y;
        }
        __syncthreads();
    }
    float mean = red2[0].x * (1.0f / DMODEL);
    float var  = red2[0].y * (1.0f / DMODEL) - mean * mean;
    float rstd = rsqrtf(var + LN_EPS);

    #pragma unroll
    for (int i = 0; i < 3; i++) {
        int d = tid + i * 256;
        sh[d] = (sx[d] - mean) * rstd * ln1g[d] + ln1b[d];
    }
    __syncthreads();

    // v = LN1(x) @ Wv + bv
    {
        int j = tid & 63, part = tid >> 6;
        float acc = 0.0f;
        int kbeg = part * 192;
        #pragma unroll 8
        for (int k = kbeg; k < kbeg + 192; ++k) acc += sh[k] * Wv[k * HDIM + j];
        red2[tid].x = acc;
        __syncthreads();
        if (tid < 64)
            sv[tid] = red2[tid].x + red2[tid + 64].x + red2[tid + 128].x + red2[tid + 192].x + bv[tid];
        __syncthreads();
    }

    // x1 = x + tile(v); LN2 stats
    float xs = 0.0f, xsq = 0.0f;
    #pragma unroll
    for (int i = 0; i < 3; i++) {
        int d = tid + i * 256;
        float v1 = sx[d] + sv[d & 63];
        out[(size_t)t * DMODEL + d] = v1;
        sx[d] = v1;
        xs += v1; xsq += v1 * v1;
    }
    __syncthreads();
    red2[tid] = make_float2(xs, xsq);
    __syncthreads();
    for (int o = 128; o > 0; o >>= 1) {
        if (tid < o) {
            red2[tid].x += red2[tid + o].x;
            red2[tid].y += red2[tid + o].y;
        }
        __syncthreads();
    }
    float mean2 = red2[0].x * (1.0f / DMODEL);
    float var2  = red2[0].y * (1.0f / DMODEL) - mean2 * mean2;
    float rstd2 = rsqrtf(var2 + LN_EPS);

    #pragma unroll
    for (int i = 0; i < 3; i++) {
        int d = tid + i * 256;
        float h2 = (sx[d] - mean2) * rstd2 * ln2g[d] + ln2b[d];
        g_h2[(size_t)t * DMODEL + d] = h2;
        sh[d] = h2;
    }
    __syncthreads();

    // gating + argmax
    {
        int je = tid & 7, pe = tid >> 3;
        float acc = 0.0f;
        int kbeg = pe * 24;
        #pragma unroll
        for (int k = kbeg; k < kbeg + 24; ++k) acc += sh[k] * Wg[k * NEXP + je];
        red2[tid].x = acc;
        __syncthreads();
        if (tid < NEXP) {
            float lsum = bg[tid];
            #pragma unroll
            for (int p = 0; p < 32; ++p) lsum += red2[p * 8 + tid].x;
            slog[tid] = lsum;
        }
        __syncthreads();
        if (tid == 0) {
            int best = 0;
            float bvl = slog[0];
            #pragma unroll
            for (int e = 1; e < NEXP; ++e)
                if (slog[e] > bvl) { bvl = slog[e]; best = e; }
            g_top1[t] = best;
        }
    }
}

// ---------------- K2: route/compact ----------------
__global__ __launch_bounds__(512) void k_route()
{
    __shared__ int cnt[NEXP];
    __shared__ int base[NEXP];
    int tid = threadIdx.x;
    if (tid < NEXP) cnt[tid] = 0;
    __syncthreads();
    for (int t = tid; t < T_TOK; t += 512) atomicAdd(&cnt[g_top1[t]], 1);
    __syncthreads();
    if (tid == 0) {
        int s = 0;
        for (int e = 0; e < NEXP; ++e) { base[e] = s; g_off[e] = s; s += cnt[e]; }
        g_off[NEXP] = s;
    }
    __syncthreads();
    if (tid < NEXP) cnt[tid] = 0;
    __syncthreads();
    for (int t = tid; t < T_TOK; t += 512) {
        int e = g_top1[t];
        int pos = base[e] + atomicAdd(&cnt[e], 1);
        g_perm[pos] = t;
    }
}

// ======== shared GEMM machinery (128x64x32, 256 thr, double-buffered) ========

struct Frag { float4 a[4]; float4 b[2]; };

__device__ __forceinline__ void ld_tiles(
    Frag& f, const float* __restrict__ Arow, bool avalid, int k0,
    const float* __restrict__ Wb, int ldw, int n0, int tid)
{
    const int ah = tid & 1;
    #pragma unroll
    for (int v = 0; v < 4; v++)
        f.a[v] = avalid ? *(const float4*)(Arow + k0 + ah * 16 + v * 4)
                        : make_float4(0.f, 0.f, 0.f, 0.f);
    const int br = tid >> 4, bc = tid & 15;
    #pragma unroll
    for (int it = 0; it < 2; it++) {
        int kr = br + it * 16;
        f.b[it] = *(const float4*)(Wb + (size_t)(k0 + kr) * ldw + n0 + bc * 4);
    }
}

__device__ __forceinline__ void st_tiles(const Frag& f, uint32_t* As, uint32_t* Bs, int tid)
{
    const int ar = tid >> 1, ah = tid & 1;
    #pragma unroll
    for (int v = 0; v < 4; v++) {
        int kk = ah * 16 + v * 4;
        As[(kk + 0) * PADA + ar] = f2tf(f.a[v].x);
        As[(kk + 1) * PADA + ar] = f2tf(f.a[v].y);
        As[(kk + 2) * PADA + ar] = f2tf(f.a[v].z);
        As[(kk + 3) * PADA + ar] = f2tf(f.a[v].w);
    }
    const int br = tid >> 4, bc = tid & 15;
    #pragma unroll
    for (int it = 0; it < 2; it++) {
        int kr = br + it * 16;
        uint4 u;
        u.x = f2tf(f.b[it].x); u.y = f2tf(f.b[it].y);
        u.z = f2tf(f.b[it].z); u.w = f2tf(f.b[it].w);
        *(uint4*)&Bs[kr * PADB + bc * 4] = u;
    }
}

__device__ __forceinline__ void compute_tile(
    float C[2][4][4], const uint32_t* As, const uint32_t* Bs,
    int wm, int wn, int grp, int tg)
{
    #pragma unroll
    for (int ks = 0; ks < 4; ks++) {
        const int kb = ks * 8;
        uint32_t a[2][4], b[4][2];
        #pragma unroll
        for (int i = 0; i < 2; i++) {
            int r = wm + i * 16 + grp;
            a[i][0] = As[(kb + tg) * PADA + r];
            a[i][1] = As[(kb + tg) * PADA + r + 8];
            a[i][2] = As[(kb + tg + 4) * PADA + r];
            a[i][3] = As[(kb + tg + 4) * PADA + r + 8];
        }
        #pragma unroll
        for (int j = 0; j < 4; j++) {
            int n = wn + j * 8 + grp;
            b[j][0] = Bs[(kb + tg) * PADB + n];
            b[j][1] = Bs[(kb + tg + 4) * PADB + n];
        }
        #pragma unroll
        for (int i = 0; i < 2; i++)
            #pragma unroll
            for (int j = 0; j < 4; j++)
                mma_tf32(C[i][j], a[i], b[j]);
    }
}

// ---------------- K3: mid = gelu(h2[perm] @ W1[e] + b1[e]) ----------------
__global__ __launch_bounds__(256) void k_ffn1(
    const float* __restrict__ W1, const float* __restrict__ b1)
{
    const int e   = blockIdx.z;
    const int off = g_off[e];
    const int Me  = g_off[e + 1] - off;
    const int m0  = blockIdx.y * BM;
    if (m0 >= Me) return;
    const int n0  = blockIdx.x * BN;

    extern __shared__ uint32_t smem[];
    uint32_t* As[2] = { smem, smem + A_ELEMS + B_ELEMS };
    uint32_t* Bs[2] = { smem + A_ELEMS, smem + 2 * A_ELEMS + B_ELEMS };

    const int tid  = threadIdx.x;
    const int lane = tid & 31, wid = tid >> 5;
    const int wm = (wid >> 1) * 32, wn = (wid & 1) * 32;
    const int grp = lane >> 2, tg = lane & 3;

    float C[2][4][4];
    #pragma unroll
    for (int i = 0; i < 2; i++)
        #pragma unroll
        for (int j = 0; j < 4; j++)
            #pragma unroll
            for (int q = 0; q < 4; q++) C[i][j][q] = 0.0f;

    const int ar = tid >> 1;
    const bool avalid = (m0 + ar) < Me;
    const int tok = avalid ? g_perm[off + m0 + ar] : 0;
    const float* Arow = g_h2 + (size_t)tok * DMODEL;
    const float* Wb = W1 + (size_t)e * DMODEL * FFDIM;

    Frag f;
    ld_tiles(f, Arow, avalid, 0, Wb, FFDIM, n0, tid);
    st_tiles(f, As[0], Bs[0], tid);
    __syncthreads();

    int cur = 0;
    #pragma unroll 1
    for (int it = 1; it < DMODEL / BK; ++it) {
        ld_tiles(f, Arow, avalid, it * BK, Wb, FFDIM, n0, tid);
        compute_tile(C, As[cur], Bs[cur], wm, wn, grp, tg);
        st_tiles(f, As[cur ^ 1], Bs[cur ^ 1], tid);
        __syncthreads();
        cur ^= 1;
    }
    compute_tile(C, As[cur], Bs[cur], wm, wn, grp, tg);

    // epilogue: +b1, gelu, store mid
    const float* bb = b1 + (size_t)e * FFDIM + n0;
    #pragma unroll
    for (int i = 0; i < 2; i++) {
        int r_lo = wm + i * 16 + grp;
        int r_hi = r_lo + 8;
        #pragma unroll
        for (int j = 0; j < 4; j++) {
            int nc = wn + j * 8 + tg * 2;
            if (m0 + r_lo < Me) {
                size_t base = (size_t)(off + m0 + r_lo) * FFDIM + n0 + nc;
                g_mid[base]     = gelu_f(C[i][j][0] + bb[nc]);
                g_mid[base + 1] = gelu_f(C[i][j][1] + bb[nc + 1]);
            }
            if (m0 + r_hi < Me) {
                size_t base = (size_t)(off + m0 + r_hi) * FFDIM + n0 + nc;
                g_mid[base]     = gelu_f(C[i][j][2] + bb[nc]);
                g_mid[base + 1] = gelu_f(C[i][j][3] + bb[nc + 1]);
            }
        }
    }
}

// ---------------- K4: out[perm] += mid @ W2[e] + b2[e]  (split-K, atomicAdd) ------
__global__ __launch_bounds__(256) void k_ffn2(
    const float* __restrict__ W2, const float* __restrict__ b2,
    float* __restrict__ out)
{
    const int z   = blockIdx.z;
    const int e   = z >> 2;
    const int spl = z & 3;
    const int off = g_off[e];
    const int Me  = g_off[e + 1] - off;
    const int m0  = blockIdx.y * BM;
    if (m0 >= Me) return;
    const int n0  = blockIdx.x * BN;
    const int kbase = spl * (FFDIM / NSPLIT);   // 768 per split

    extern __shared__ uint32_t smem[];
    uint32_t* As[2] = { smem, smem + A_ELEMS + B_ELEMS };
    uint32_t* Bs[2] = { smem + A_ELEMS, smem + 2 * A_ELEMS + B_ELEMS };

    const int tid  = threadIdx.x;
    const int lane = tid & 31, wid = tid >> 5;
    const int wm = (wid >> 1) * 32, wn = (wid & 1) * 32;
    const int grp = lane >> 2, tg = lane & 3;

    float C[2][4][4];
    #pragma unroll
    for (int i = 0; i < 2; i++)
        #pragma unroll
        for (int j = 0; j < 4; j++)
            #pragma unroll
            for (int q = 0; q < 4; q++) C[i][j][q] = 0.0f;

    const int ar = tid >> 1;
    const bool avalid = (m0 + ar) < Me;
    const int row = avalid ? (off + m0 + ar) : 0;
    const float* Arow = g_mid + (size_t)row * FFDIM + kbase;
    const float* Wb = W2 + (size_t)e * FFDIM * DMODEL + (size_t)kbase * DMODEL;

    Frag f;
    ld_tiles(f, Arow, avalid, 0, Wb, DMODEL, n0, tid);
    st_tiles(f, As[0], Bs[0], tid);
    __syncthreads();

    int cur = 0;
    #pragma unroll 1
    for (int it = 1; it < (FFDIM / NSPLIT) / BK; ++it) {
        ld_tiles(f, Arow, avalid, it * BK, Wb, DMODEL, n0, tid);
        compute_tile(C, As[cur], Bs[cur], wm, wn, grp, tg);
        st_tiles(f, As[cur ^ 1], Bs[cur ^ 1], tid);
        __syncthreads();
        cur ^= 1;
    }
    compute_tile(C, As[cur], Bs[cur], wm, wn, grp, tg);

    // epilogue: +b2 (split 0 only), scatter-add into residual out[token]
    const float* bb = b2 + (size_t)e * DMODEL + n0;
    const float bscale = (spl == 0) ? 1.0f : 0.0f;
    #pragma unroll
    for (int i = 0; i < 2; i++) {
        int r_lo = wm + i * 16 + grp;
        int r_hi = r_lo + 8;
        #pragma unroll
        for (int j = 0; j < 4; j++) {
            int nc = wn + j * 8 + tg * 2;
            if (m0 + r_lo < Me) {
                int tok = g_perm[off + m0 + r_lo];
                float* o = out + (size_t)tok * DMODEL + n0 + nc;
                atomicAdd(&o[0], C[i][j][0] + bscale * bb[nc]);
                atomicAdd(&o[1], C[i][j][1] + bscale * bb[nc + 1]);
            }
            if (m0 + r_hi < Me) {
                int tok = g_perm[off + m0 + r_hi];
                float* o = out + (size_t)tok * DMODEL + n0 + nc;
                atomicAdd(&o[0], C[i][j][2] + bscale * bb[nc]);
                atomicAdd(&o[1], C[i][j][3] + bscale * bb[nc + 1]);
            }
        }
    }
}

// ---------------- launch ----------------
extern "C" void kernel_launch(void* const* d_in, const int* in_sizes, int n_in,
                              void* d_out, int out_size)
{
    (void)in_sizes; (void)n_in; (void)out_size;
    const float* x    = (const float*)d_in[0];
    const float* ln1g = (const float*)d_in[1];
    const float* ln1b = (const float*)d_in[2];
    // d_in[3..6] = Wq,bq,Wk,bk : analytically cancelled
    const float* Wv   = (const float*)d_in[7];
    const float* bv   = (const float*)d_in[8];
    const float* ln2g = (const float*)d_in[9];
    const float* ln2b = (const float*)d_in[10];
    const float* Wg   = (const float*)d_in[11];
    const float* bg   = (const float*)d_in[12];
    const float* W1   = (const float*)d_in[13];
    const float* b1   = (const float*)d_in[14];
    const float* W2   = (const float*)d_in[15];
    const float* b2   = (const float*)d_in[16];
    float* out = (float*)d_out;

    static bool attr_done = false;
    if (!attr_done) {
        cudaFuncSetAttribute(k_ffn1, cudaFuncAttributeMaxDynamicSharedMemorySize, SMEM_BYTES);
        cudaFuncSetAttribute(k_ffn2, cudaFuncAttributeMaxDynamicSharedMemorySize, SMEM_BYTES);
        attr_done = true;
    }

    k_pre<<<T_TOK, 256>>>(x, ln1g, ln1b, Wv, bv, ln2g, ln2b, Wg, bg, out);
    k_route<<<1, 512>>>();
    k_ffn1<<<dim3(FFDIM / BN, MT128, NEXP), 256, SMEM_BYTES>>>(W1, b1);
    k_ffn2<<<dim3(DMODEL / BN, MT128, NEXP * NSPLIT), 256, SMEM_BYTES>>>(W2, b2, out);
}

// round 4
// speedup vs baseline: 2.7895x; 1.4075x over previous
#include <cuda_runtime.h>
#include <cstdint>
#include <cstddef>

#define T_TOK 1568
#define DMODEL 768
#define HDIM   64
#define NEXP   8
#define FFDIM  3072
#define LN_EPS 1e-5f

// GEMM geometry: CTA 128x128x32, 4 warps of 64x64
#define BM 128
#define BN 128
#define BK 32
#define BPAD 136                       // B row stride in words (136 % 32 == 8 -> conflict-free)
#define A_BYTES (BM * 128)             // 16384
#define B_BYTES (BK * BPAD * 4)        // 17408
#define STAGE_BYTES (A_BYTES + B_BYTES)
#define NSTAGE 3
#define SMEM_TOT (NSTAGE * STAGE_BYTES)
#define MT128 ((T_TOK + BM - 1) / BM)  // 13
#define NSPLIT 3                       // ffn2 split-K (1024 each)

// ---------------- static scratch ----------------
__device__ float g_h2[(size_t)T_TOK * DMODEL];
__device__ float g_mid[(size_t)T_TOK * FFDIM];
__device__ float g_part[(size_t)NSPLIT * T_TOK * DMODEL];
__device__ int   g_top1[T_TOK];
__device__ int   g_perm[T_TOK];
__device__ int   g_inv[T_TOK];
__device__ int   g_off[NEXP + 1];

// ---------------- helpers ----------------
__device__ __forceinline__ float gelu_f(float v) {
    return 0.5f * v * (1.0f + erff(v * 0.70710678118654752440f));
}

__device__ __forceinline__ uint32_t smem_u32(const void* p) {
    uint32_t a;
    asm("{ .reg .u64 t; cvta.to.shared.u64 t, %1; cvt.u32.u64 %0, t; }" : "=r"(a) : "l"(p));
    return a;
}

__device__ __forceinline__ uint32_t f2tf_u(uint32_t x) {
    uint32_t u;
    float f = __uint_as_float(x);
    asm("cvt.rna.tf32.f32 %0, %1;" : "=r"(u) : "f"(f));
    return u;
}

__device__ __forceinline__ uint32_t lds_u32(uint32_t addr) {
    uint32_t v;
    asm volatile("ld.shared.b32 %0, [%1];" : "=r"(v) : "r"(addr));
    return v;
}

__device__ __forceinline__ void ldsm4(uint32_t r[4], uint32_t addr) {
    asm volatile("ldmatrix.sync.aligned.m8n8.x4.shared.b16 {%0,%1,%2,%3}, [%4];"
                 : "=r"(r[0]), "=r"(r[1]), "=r"(r[2]), "=r"(r[3]) : "r"(addr));
}

__device__ __forceinline__ void mma_tf32(float c[4], const uint32_t a[4], const uint32_t b[2]) {
    asm volatile(
        "mma.sync.aligned.m16n8k8.row.col.f32.tf32.tf32.f32 "
        "{%0,%1,%2,%3},{%4,%5,%6,%7},{%8,%9},{%0,%1,%2,%3};\n"
        : "+f"(c[0]), "+f"(c[1]), "+f"(c[2]), "+f"(c[3])
        : "r"(a[0]), "r"(a[1]), "r"(a[2]), "r"(a[3]), "r"(b[0]), "r"(b[1]));
}

#define CP16(dst, src, sz) \
    asm volatile("cp.async.cg.shared.global [%0], [%1], 16, %2;" \
                 :: "r"(dst), "l"(src), "r"(sz))
#define CP_COMMIT() asm volatile("cp.async.commit_group;" ::: "memory")

template<int N> __device__ __forceinline__ void cp_wait() {
    asm volatile("cp.async.wait_group %0;" :: "n"(N) : "memory");
}

// ---------------- staging: one K-tile (A 128x32 swizzled rows, B 32x128 k-major) ----
__device__ __forceinline__ void stage_issue(
    uint32_t sbase, const float* __restrict__ arow, int asz,
    const float* __restrict__ wblk, size_t ldw, int tid)
{
    // A: thread = one row, 8 x 16B, XOR-swizzled chunks
    uint32_t adst = sbase + tid * 128;
    const int sw = tid & 7;
    #pragma unroll
    for (int c = 0; c < 8; c++)
        CP16(adst + ((c ^ sw) << 4), arow + c * 4, asz);
    // B: k-major rows (128 floats data, row stride 544B), thread covers nc=(tid&31), k=(tid>>5)+4i
    uint32_t bdst = sbase + A_BYTES + (tid & 31) * 16;
    const float* wsrc = wblk + (size_t)(tid >> 5) * ldw + (tid & 31) * 4;
    #pragma unroll
    for (int i = 0; i < 8; i++)
        CP16(bdst + (uint32_t)((tid >> 5) + 4 * i) * (BPAD * 4), wsrc + (size_t)(4 * i) * ldw, 16);
}

// ---------------- compute one K-tile: 4 ks-steps of m16n8k8, warp 64x64 ----------
__device__ __forceinline__ void compute_stage(
    float C[4][8][4], uint32_t abase, uint32_t bbase, int wm, int wn, int lane)
{
    const int grp = lane >> 2, tg = lane & 3;
    const uint32_t arow_base = abase + (uint32_t)(wm + (lane & 15)) * 128;
    const int asw = lane & 7;
    const int aq = lane >> 4;
    #pragma unroll
    for (int ks = 0; ks < 4; ks++) {
        uint32_t a[4][4];
        #pragma unroll
        for (int i = 0; i < 4; i++)
            ldsm4(a[i], arow_base + i * 2048 + (uint32_t)((((ks << 1) | aq) ^ asw) << 4));
        uint32_t b[8][2];
        uint32_t brow0 = bbase + (uint32_t)((ks * 8 + tg) * BPAD) * 4;
        uint32_t brow1 = brow0 + 4 * BPAD * 4;
        #pragma unroll
        for (int j = 0; j < 8; j++) {
            uint32_t nw = (uint32_t)(wn + j * 8 + grp) * 4;
            b[j][0] = lds_u32(brow0 + nw);
            b[j][1] = lds_u32(brow1 + nw);
        }
        #pragma unroll
        for (int i = 0; i < 4; i++)
            #pragma unroll
            for (int q = 0; q < 4; q++)
                a[i][q] = f2tf_u(a[i][q]);
        #pragma unroll
        for (int j = 0; j < 8; j++) {
            b[j][0] = f2tf_u(b[j][0]);
            b[j][1] = f2tf_u(b[j][1]);
        }
        #pragma unroll
        for (int i = 0; i < 4; i++)
            #pragma unroll
            for (int j = 0; j < 8; j++)
                mma_tf32(C[i][j], a[i], b[j]);
    }
}

// ---------------- K1: LN1 + v GEMV + residual + LN2 + gating/argmax (4 tokens/block) --
// attention out == v exactly (k,v broadcast over heads -> uniform softmax);
// gating softmax monotone -> argmax of raw logits.
__global__ __launch_bounds__(256) void k_pre(
    const float* __restrict__ x,
    const float* __restrict__ ln1g, const float* __restrict__ ln1b,
    const float* __restrict__ Wv,   const float* __restrict__ bv,
    const float* __restrict__ ln2g, const float* __restrict__ ln2b,
    const float* __restrict__ Wg,   const float* __restrict__ bg,
    float* __restrict__ out)
{
    const int t0 = blockIdx.x * 4;
    const int tid = threadIdx.x;

    __shared__ float sx[4][DMODEL];
    __shared__ float sh[4][DMODEL];
    __shared__ float4 rs[256], rq[256];
    __shared__ float sv[4][HDIM];
    __shared__ float slog[4][NEXP];

    float s[4], q[4];
    #pragma unroll
    for (int tt = 0; tt < 4; tt++) {
        const float* xr = x + (size_t)(t0 + tt) * DMODEL;
        float v0 = xr[tid], v1 = xr[tid + 256], v2 = xr[tid + 512];
        sx[tt][tid] = v0; sx[tt][tid + 256] = v1; sx[tt][tid + 512] = v2;
        s[tt] = v0 + v1 + v2;
        q[tt] = v0 * v0 + v1 * v1 + v2 * v2;
    }
    rs[tid] = make_float4(s[0], s[1], s[2], s[3]);
    rq[tid] = make_float4(q[0], q[1], q[2], q[3]);
    __syncthreads();
    for (int o = 128; o > 0; o >>= 1) {
        if (tid < o) {
            float4 a = rs[tid], b = rs[tid + o];
            rs[tid] = make_float4(a.x + b.x, a.y + b.y, a.z + b.z, a.w + b.w);
            float4 c = rq[tid], d = rq[tid + o];
            rq[tid] = make_float4(c.x + d.x, c.y + d.y, c.z + d.z, c.w + d.w);
        }
        __syncthreads();
    }
    float mean[4], rstd[4];
    {
        float4 sm = rs[0], sq = rq[0];
        const float* smp = &sm.x; const float* sqp = &sq.x;
        #pragma unroll
        for (int tt = 0; tt < 4; tt++) {
            mean[tt] = smp[tt] * (1.0f / DMODEL);
            float var = sqp[tt] * (1.0f / DMODEL) - mean[tt] * mean[tt];
            rstd[tt] = rsqrtf(var + LN_EPS);
        }
    }
    __syncthreads();
    #pragma unroll
    for (int i = 0; i < 3; i++) {
        int d = tid + i * 256;
        float g = ln1g[d], b = ln1b[d];
        #pragma unroll
        for (int tt = 0; tt < 4; tt++)
            sh[tt][d] = (sx[tt][d] - mean[tt]) * rstd[tt] * g + b;
    }
    __syncthreads();

    // v = LN1(x) @ Wv + bv (shared Wv loads across 4 tokens)
    {
        const int j = tid & 63, part = tid >> 6;
        float acc[4] = {0.f, 0.f, 0.f, 0.f};
        const int kbeg = part * 192;
        for (int k = kbeg; k < kbeg + 192; ++k) {
            float w = Wv[k * HDIM + j];
            #pragma unroll
            for (int tt = 0; tt < 4; tt++) acc[tt] += sh[tt][k] * w;
        }
        rs[tid] = make_float4(acc[0], acc[1], acc[2], acc[3]);
        __syncthreads();
        if (tid < 64) {
            float4 a = rs[tid], b = rs[tid + 64], c = rs[tid + 128], d = rs[tid + 192];
            float bvv = bv[tid];
            sv[0][tid] = a.x + b.x + c.x + d.x + bvv;
            sv[1][tid] = a.y + b.y + c.y + d.y + bvv;
            sv[2][tid] = a.z + b.z + c.z + d.z + bvv;
            sv[3][tid] = a.w + b.w + c.w + d.w + bvv;
        }
        __syncthreads();
    }

    // x1 = x + tile(v); LN2 stats
    #pragma unroll
    for (int tt = 0; tt < 4; tt++) { s[tt] = 0.f; q[tt] = 0.f; }
    #pragma unroll
    for (int i = 0; i < 3; i++) {
        int d = tid + i * 256;
        #pragma unroll
        for (int tt = 0; tt < 4; tt++) {
            float v1 = sx[tt][d] + sv[tt][d & 63];
            out[(size_t)(t0 + tt) * DMODEL + d] = v1;
            sx[tt][d] = v1;
            s[tt] += v1; q[tt] += v1 * v1;
        }
    }
    rs[tid] = make_float4(s[0], s[1], s[2], s[3]);
    rq[tid] = make_float4(q[0], q[1], q[2], q[3]);
    __syncthreads();
    for (int o = 128; o > 0; o >>= 1) {
        if (tid < o) {
            float4 a = rs[tid], b = rs[tid + o];
            rs[tid] = make_float4(a.x + b.x, a.y + b.y, a.z + b.z, a.w + b.w);
            float4 c = rq[tid], d = rq[tid + o];
            rq[tid] = make_float4(c.x + d.x, c.y + d.y, c.z + d.z, c.w + d.w);
        }
        __syncthreads();
    }
    {
        float4 sm = rs[0], sq = rq[0];
        const float* smp = &sm.x; const float* sqp = &sq.x;
        #pragma unroll
        for (int tt = 0; tt < 4; tt++) {
            mean[tt] = smp[tt] * (1.0f / DMODEL);
            float var = sqp[tt] * (1.0f / DMODEL) - mean[tt] * mean[tt];
            rstd[tt] = rsqrtf(var + LN_EPS);
        }
    }
    __syncthreads();
    #pragma unroll
    for (int i = 0; i < 3; i++) {
        int d = tid + i * 256;
        float g = ln2g[d], b = ln2b[d];
        #pragma unroll
        for (int tt = 0; tt < 4; tt++) {
            float h2 = (sx[tt][d] - mean[tt]) * rstd[tt] * g + b;
            g_h2[(size_t)(t0 + tt) * DMODEL + d] = h2;
            sh[tt][d] = h2;
        }
    }
    __syncthreads();

    // gating logits + argmax
    {
        const int je = tid & 7, pe = tid >> 3;
        float acc[4] = {0.f, 0.f, 0.f, 0.f};
        const int kbeg = pe * 24;
        for (int k = kbeg; k < kbeg + 24; ++k) {
            float w = Wg[k * NEXP + je];
            #pragma unroll
            for (int tt = 0; tt < 4; tt++) acc[tt] += sh[tt][k] * w;
        }
        rs[tid] = make_float4(acc[0], acc[1], acc[2], acc[3]);
        __syncthreads();
        if (tid < NEXP) {
            float4 l = make_float4(0.f, 0.f, 0.f, 0.f);
            #pragma unroll
            for (int p = 0; p < 32; ++p) {
                float4 a = rs[p * 8 + tid];
                l.x += a.x; l.y += a.y; l.z += a.z; l.w += a.w;
            }
            float bgv = bg[tid];
            slog[0][tid] = l.x + bgv;
            slog[1][tid] = l.y + bgv;
            slog[2][tid] = l.z + bgv;
            slog[3][tid] = l.w + bgv;
        }
        __syncthreads();
        if (tid < 4) {
            int best = 0;
            float bvl = slog[tid][0];
            #pragma unroll
            for (int e = 1; e < NEXP; ++e)
                if (slog[tid][e] > bvl) { bvl = slog[tid][e]; best = e; }
            g_top1[t0 + tid] = best;
        }
    }
}

// ---------------- K2: route/compact ----------------
__global__ __launch_bounds__(512) void k_route()
{
    __shared__ int cnt[NEXP];
    __shared__ int base[NEXP];
    int tid = threadIdx.x;
    if (tid < NEXP) cnt[tid] = 0;
    __syncthreads();
    for (int t = tid; t < T_TOK; t += 512) atomicAdd(&cnt[g_top1[t]], 1);
    __syncthreads();
    if (tid == 0) {
        int s = 0;
        for (int e = 0; e < NEXP; ++e) { base[e] = s; g_off[e] = s; s += cnt[e]; }
        g_off[NEXP] = s;
    }
    __syncthreads();
    if (tid < NEXP) cnt[tid] = 0;
    __syncthreads();
    for (int t = tid; t < T_TOK; t += 512) {
        int e = g_top1[t];
        int pos = base[e] + atomicAdd(&cnt[e], 1);
        g_perm[pos] = t;
        g_inv[t] = pos;
    }
}

// ---------------- K3: mid = gelu(h2[perm] @ W1[e] + b1[e]) ----------------
__global__ __launch_bounds__(128) void k_ffn1(
    const float* __restrict__ W1, const float* __restrict__ b1)
{
    const int e   = blockIdx.z;
    const int off = g_off[e];
    const int Me  = g_off[e + 1] - off;
    const int m0  = blockIdx.y * BM;
    if (m0 >= Me) return;
    const int n0  = blockIdx.x * BN;

    extern __shared__ char smem[];
    const uint32_t sb = smem_u32(smem);

    const int tid = threadIdx.x, lane = tid & 31, wid = tid >> 5;
    const int wm = (wid >> 1) * 64, wn = (wid & 1) * 64;

    const bool av = (m0 + tid) < Me;
    const float* arow = g_h2 + (size_t)(av ? g_perm[off + m0 + tid] : 0) * DMODEL;
    const int asz = av ? 16 : 0;
    const float* wblk = W1 + (size_t)e * DMODEL * FFDIM + n0;

    float C[4][8][4];
    #pragma unroll
    for (int i = 0; i < 4; i++)
        #pragma unroll
        for (int j = 0; j < 8; j++)
            #pragma unroll
            for (int qq = 0; qq < 4; qq++) C[i][j][qq] = 0.0f;

    stage_issue(sb,               arow,      asz, wblk,                         FFDIM, tid); CP_COMMIT();
    stage_issue(sb + STAGE_BYTES, arow + 32, asz, wblk + (size_t)32 * FFDIM,    FFDIM, tid); CP_COMMIT();

    const int NK = DMODEL / BK;   // 24
    for (int it = 0; it < NK; ++it) {
        if (it + 2 < NK) {
            uint32_t s2 = sb + (uint32_t)((it + 2) % 3) * STAGE_BYTES;
            stage_issue(s2, arow + (it + 2) * 32, asz,
                        wblk + (size_t)(it + 2) * 32 * FFDIM, FFDIM, tid);
            CP_COMMIT();
            cp_wait<2>();
        } else if (it + 1 < NK) cp_wait<1>();
        else cp_wait<0>();
        __syncthreads();
        uint32_t sc = sb + (uint32_t)(it % 3) * STAGE_BYTES;
        compute_stage(C, sc, sc + A_BYTES, wm, wn, lane);
        __syncthreads();
    }

    // epilogue: +b1, gelu, store
    const int grp = lane >> 2, tg = lane & 3;
    const float* bb = b1 + (size_t)e * FFDIM + n0;
    #pragma unroll
    for (int i = 0; i < 4; i++) {
        int r_lo = wm + i * 16 + grp;
        int r_hi = r_lo + 8;
        bool v_lo = (m0 + r_lo) < Me, v_hi = (m0 + r_hi) < Me;
        float* d_lo = g_mid + (size_t)(off + m0 + r_lo) * FFDIM + n0;
        float* d_hi = g_mid + (size_t)(off + m0 + r_hi) * FFDIM + n0;
        #pragma unroll
        for (int j = 0; j < 8; j++) {
            int nc = wn + j * 8 + tg * 2;
            float b0 = bb[nc], b1v = bb[nc + 1];
            if (v_lo) {
                float2 o = make_float2(gelu_f(C[i][j][0] + b0), gelu_f(C[i][j][1] + b1v));
                *(float2*)(d_lo + nc) = o;
            }
            if (v_hi) {
                float2 o = make_float2(gelu_f(C[i][j][2] + b0), gelu_f(C[i][j][3] + b1v));
                *(float2*)(d_hi + nc) = o;
            }
        }
    }
}

// ---------------- K4: part[spl] = mid @ W2[e][kslice]  (split-K=3) ----------------
__global__ __launch_bounds__(128) void k_ffn2(const float* __restrict__ W2)
{
    const int z   = blockIdx.z;
    const int e   = z / NSPLIT;
    const int spl = z % NSPLIT;
    const int off = g_off[e];
    const int Me  = g_off[e + 1] - off;
    const int m0  = blockIdx.y * BM;
    if (m0 >= Me) return;
    const int n0  = blockIdx.x * BN;
    const int kbase = spl * (FFDIM / NSPLIT);   // 1024

    extern __shared__ char smem[];
    const uint32_t sb = smem_u32(smem);

    const int tid = threadIdx.x, lane = tid & 31, wid = tid >> 5;
    const int wm = (wid >> 1) * 64, wn = (wid & 1) * 64;

    const bool av = (m0 + tid) < Me;
    const float* arow = g_mid + (size_t)(off + (av ? m0 + tid : 0)) * FFDIM + kbase;
    const int asz = av ? 16 : 0;
    const float* wblk = W2 + (size_t)e * FFDIM * DMODEL + (size_t)kbase * DMODEL + n0;

    float C[4][8][4];
    #pragma unroll
    for (int i = 0; i < 4; i++)
        #pragma unroll
        for (int j = 0; j < 8; j++)
            #pragma unroll
            for (int qq = 0; qq < 4; qq++) C[i][j][qq] = 0.0f;

    stage_issue(sb,               arow,      asz, wblk,                      DMODEL, tid); CP_COMMIT();
    stage_issue(sb + STAGE_BYTES, arow + 32, asz, wblk + (size_t)32 * DMODEL, DMODEL, tid); CP_COMMIT();

    const int NK = (FFDIM / NSPLIT) / BK;   // 32
    for (int it = 0; it < NK; ++it) {
        if (it + 2 < NK) {
            uint32_t s2 = sb + (uint32_t)((it + 2) % 3) * STAGE_BYTES;
            stage_issue(s2, arow + (it + 2) * 32, asz,
                        wblk + (size_t)(it + 2) * 32 * DMODEL, DMODEL, tid);
            CP_COMMIT();
            cp_wait<2>();
        } else if (it + 1 < NK) cp_wait<1>();
        else cp_wait<0>();
        __syncthreads();
        uint32_t sc = sb + (uint32_t)(it % 3) * STAGE_BYTES;
        compute_stage(C, sc, sc + A_BYTES, wm, wn, lane);
        __syncthreads();
    }

    // epilogue: store partials (no bias here)
    const int grp = lane >> 2, tg = lane & 3;
    float* pbase = g_part + (size_t)spl * T_TOK * DMODEL;
    #pragma unroll
    for (int i = 0; i < 4; i++) {
        int r_lo = wm + i * 16 + grp;
        int r_hi = r_lo + 8;
        bool v_lo = (m0 + r_lo) < Me, v_hi = (m0 + r_hi) < Me;
        float* d_lo = pbase + (size_t)(off + m0 + r_lo) * DMODEL + n0;
        float* d_hi = pbase + (size_t)(off + m0 + r_hi) * DMODEL + n0;
        #pragma unroll
        for (int j = 0; j < 8; j++) {
            int nc = wn + j * 8 + tg * 2;
            if (v_lo) *(float2*)(d_lo + nc) = make_float2(C[i][j][0], C[i][j][1]);
            if (v_hi) *(float2*)(d_hi + nc) = make_float2(C[i][j][2], C[i][j][3]);
        }
    }
}

// ---------------- K5: out[t] += part0 + part1 + part2 + b2[e] ----------------
__global__ __launch_bounds__(192) void k_fin(const float* __restrict__ b2,
                                             float* __restrict__ out)
{
    const int t = blockIdx.x;
    const int c = threadIdx.x * 4;
    const int r = g_inv[t];
    const int e = g_top1[t];
    float4 p0 = *(const float4*)(g_part + (size_t)r * DMODEL + c);
    float4 p1 = *(const float4*)(g_part + ((size_t)T_TOK + r) * DMODEL + c);
    float4 p2 = *(const float4*)(g_part + ((size_t)2 * T_TOK + r) * DMODEL + c);
    float4 bb = *(const float4*)(b2 + (size_t)e * DMODEL + c);
    float4 o  = *(float4*)(out + (size_t)t * DMODEL + c);
    o.x += p0.x + p1.x + p2.x + bb.x;
    o.y += p0.y + p1.y + p2.y + bb.y;
    o.z += p0.z + p1.z + p2.z + bb.z;
    o.w += p0.w + p1.w + p2.w + bb.w;
    *(float4*)(out + (size_t)t * DMODEL + c) = o;
}

// ---------------- launch ----------------
extern "C" void kernel_launch(void* const* d_in, const int* in_sizes, int n_in,
                              void* d_out, int out_size)
{
    (void)in_sizes; (void)n_in; (void)out_size;
    const float* x    = (const float*)d_in[0];
    const float* ln1g = (const float*)d_in[1];
    const float* ln1b = (const float*)d_in[2];
    // d_in[3..6] = Wq,bq,Wk,bk : analytically cancelled
    const float* Wv   = (const float*)d_in[7];
    const float* bv   = (const float*)d_in[8];
    const float* ln2g = (const float*)d_in[9];
    const float* ln2b = (const float*)d_in[10];
    const float* Wg   = (const float*)d_in[11];
    const float* bg   = (const float*)d_in[12];
    const float* W1   = (const float*)d_in[13];
    const float* b1   = (const float*)d_in[14];
    const float* W2   = (const float*)d_in[15];
    const float* b2   = (const float*)d_in[16];
    float* out = (float*)d_out;

    static bool attr_done = false;
    if (!attr_done) {
        cudaFuncSetAttribute(k_ffn1, cudaFuncAttributeMaxDynamicSharedMemorySize, SMEM_TOT);
        cudaFuncSetAttribute(k_ffn2, cudaFuncAttributeMaxDynamicSharedMemorySize, SMEM_TOT);
        attr_done = true;
    }

    k_pre<<<T_TOK / 4, 256>>>(x, ln1g, ln1b, Wv, bv, ln2g, ln2b, Wg, bg, out);
    k_route<<<1, 512>>>();
    k_ffn1<<<dim3(FFDIM / BN, MT128, NEXP), 128, SMEM_TOT>>>(W1, b1);
    k_ffn2<<<dim3(DMODEL / BN, MT128, NEXP * NSPLIT), 128, SMEM_TOT>>>(W2);
    k_fin<<<T_TOK, 192>>>(b2, out);
}

// round 5
// speedup vs baseline: 3.7189x; 1.3331x over previous
#include <cuda_runtime.h>
#include <cstdint>
#include <cstddef>

#define T_TOK 1568
#define DMODEL 768
#define HDIM   64
#define NEXP   8
#define FFDIM  3072
#define LN_EPS 1e-5f

// GEMM geometry: CTA 128x128x32, 8 warps of 64x32
#define BM 128
#define BN 128
#define BK 32
#define BPAD 136                       // B row stride in words (136 % 32 == 8 -> conflict-free)
#define A_BYTES (BM * 128)             // 16384
#define B_BYTES (BK * BPAD * 4)        // 17408
#define STAGE_BYTES (A_BYTES + B_BYTES)
#define NSTAGE 3
#define SMEM_TOT (NSTAGE * STAGE_BYTES)
#define MT128 ((T_TOK + BM - 1) / BM)  // 13
#define NSPLIT 3                       // ffn2 split-K (1024 each)

// ---------------- static scratch ----------------
__device__ float g_h2[(size_t)T_TOK * DMODEL];
__device__ float g_mid[(size_t)T_TOK * FFDIM];
__device__ float g_part[(size_t)NSPLIT * T_TOK * DMODEL];
__device__ int   g_top1[T_TOK];
__device__ int   g_perm[T_TOK];
__device__ int   g_inv[T_TOK];
__device__ int   g_off[NEXP + 1];

// ---------------- helpers ----------------
__device__ __forceinline__ float gelu_f(float v) {
    return 0.5f * v * (1.0f + erff(v * 0.70710678118654752440f));
}

__device__ __forceinline__ uint32_t smem_u32(const void* p) {
    uint32_t a;
    asm("{ .reg .u64 t; cvta.to.shared.u64 t, %1; cvt.u32.u64 %0, t; }" : "=r"(a) : "l"(p));
    return a;
}

__device__ __forceinline__ uint32_t lds_u32(uint32_t addr) {
    uint32_t v;
    asm volatile("ld.shared.b32 %0, [%1];" : "=r"(v) : "r"(addr));
    return v;
}

__device__ __forceinline__ void ldsm4(uint32_t r[4], uint32_t addr) {
    asm volatile("ldmatrix.sync.aligned.m8n8.x4.shared.b16 {%0,%1,%2,%3}, [%4];"
                 : "=r"(r[0]), "=r"(r[1]), "=r"(r[2]), "=r"(r[3]) : "r"(addr));
}

// NOTE: operands are raw fp32 bit patterns; the tf32 MMA datapath reads the top
// 19 bits (sign/exp/10-bit mantissa) -> round-toward-zero tf32 ("fast" tf32 mode).
__device__ __forceinline__ void mma_tf32(float c[4], const uint32_t a[4], const uint32_t b[2]) {
    asm volatile(
        "mma.sync.aligned.m16n8k8.row.col.f32.tf32.tf32.f32 "
        "{%0,%1,%2,%3},{%4,%5,%6,%7},{%8,%9},{%0,%1,%2,%3};\n"
        : "+f"(c[0]), "+f"(c[1]), "+f"(c[2]), "+f"(c[3])
        : "r"(a[0]), "r"(a[1]), "r"(a[2]), "r"(a[3]), "r"(b[0]), "r"(b[1]));
}

#define CP16(dst, src, sz) \
    asm volatile("cp.async.cg.shared.global [%0], [%1], 16, %2;" \
                 :: "r"(dst), "l"(src), "r"(sz))
#define CP_COMMIT() asm volatile("cp.async.commit_group;" ::: "memory")

template<int N> __device__ __forceinline__ void cp_wait() {
    asm volatile("cp.async.wait_group %0;" :: "n"(N) : "memory");
}

// ---------------- staging (256 threads): A 128x32 swizzled rows, B 32x128 k-major ----
__device__ __forceinline__ void stage_issue(
    uint32_t sbase, const float* __restrict__ arow, int asz,
    const float* __restrict__ wblk, size_t ldw, int tid)
{
    // A: 2 threads per row; each does 4 x 16B XOR-swizzled chunks
    const int row = tid >> 1, h = tid & 1;
    uint32_t adst = sbase + row * 128;
    const int sw = row & 7;
    #pragma unroll
    for (int c = 0; c < 4; c++) {
        int cc = h * 4 + c;
        CP16(adst + ((cc ^ sw) << 4), arow + cc * 4, asz);
    }
    // B: k-major rows (128 floats data, stride 544B); thread covers col16=(tid&31), k=(tid>>5)+8i
    uint32_t bdst = sbase + A_BYTES + (tid & 31) * 16;
    const float* wsrc = wblk + (size_t)(tid >> 5) * ldw + (tid & 31) * 4;
    #pragma unroll
    for (int i = 0; i < 4; i++)
        CP16(bdst + (uint32_t)((tid >> 5) + 8 * i) * (BPAD * 4), wsrc + (size_t)(8 * i) * ldw, 16);
}

// ---------------- compute one K-tile: 4 ks-steps of m16n8k8, warp 64x32 ----------
__device__ __forceinline__ void compute_stage(
    float C[4][4][4], uint32_t abase, uint32_t bbase, int wm, int wn, int lane)
{
    const int grp = lane >> 2, tg = lane & 3;
    const uint32_t arow_base = abase + (uint32_t)(wm + (lane & 15)) * 128;
    const int asw = lane & 7;
    const int aq = lane >> 4;
    #pragma unroll
    for (int ks = 0; ks < 4; ks++) {
        uint32_t a[4][4];
        #pragma unroll
        for (int i = 0; i < 4; i++)
            ldsm4(a[i], arow_base + i * 2048 + (uint32_t)((((ks << 1) | aq) ^ asw) << 4));
        uint32_t b[4][2];
        uint32_t brow0 = bbase + (uint32_t)((ks * 8 + tg) * BPAD) * 4;
        uint32_t brow1 = brow0 + 4 * BPAD * 4;
        #pragma unroll
        for (int j = 0; j < 4; j++) {
            uint32_t nw = (uint32_t)(wn + j * 8 + grp) * 4;
            b[j][0] = lds_u32(brow0 + nw);
            b[j][1] = lds_u32(brow1 + nw);
        }
        #pragma unroll
        for (int i = 0; i < 4; i++)
            #pragma unroll
            for (int j = 0; j < 4; j++)
                mma_tf32(C[i][j], a[i], b[j]);
    }
}

// ---------------- K1: LN1 + v GEMV + residual + LN2 + gating/argmax (4 tokens/block) --
// attention out == v exactly (k,v broadcast over heads -> uniform softmax);
// gating softmax monotone -> argmax of raw logits.
__global__ __launch_bounds__(256) void k_pre(
    const float* __restrict__ x,
    const float* __restrict__ ln1g, const float* __restrict__ ln1b,
    const float* __restrict__ Wv,   const float* __restrict__ bv,
    const float* __restrict__ ln2g, const float* __restrict__ ln2b,
    const float* __restrict__ Wg,   const float* __restrict__ bg,
    float* __restrict__ out)
{
    const int t0 = blockIdx.x * 4;
    const int tid = threadIdx.x;

    __shared__ float sx[4][DMODEL];
    __shared__ float sh[4][DMODEL];
    __shared__ float4 rs[256], rq[256];
    __shared__ float sv[4][HDIM];
    __shared__ float slog[4][NEXP];

    float s[4], q[4];
    #pragma unroll
    for (int tt = 0; tt < 4; tt++) {
        const float* xr = x + (size_t)(t0 + tt) * DMODEL;
        float v0 = xr[tid], v1 = xr[tid + 256], v2 = xr[tid + 512];
        sx[tt][tid] = v0; sx[tt][tid + 256] = v1; sx[tt][tid + 512] = v2;
        s[tt] = v0 + v1 + v2;
        q[tt] = v0 * v0 + v1 * v1 + v2 * v2;
    }
    rs[tid] = make_float4(s[0], s[1], s[2], s[3]);
    rq[tid] = make_float4(q[0], q[1], q[2], q[3]);
    __syncthreads();
    for (int o = 128; o > 0; o >>= 1) {
        if (tid < o) {
            float4 a = rs[tid], b = rs[tid + o];
            rs[tid] = make_float4(a.x + b.x, a.y + b.y, a.z + b.z, a.w + b.w);
            float4 c = rq[tid], d = rq[tid + o];
            rq[tid] = make_float4(c.x + d.x, c.y + d.y, c.z + d.z, c.w + d.w);
        }
        __syncthreads();
    }
    float mean[4], rstd[4];
    {
        float4 sm = rs[0], sq = rq[0];
        const float* smp = &sm.x; const float* sqp = &sq.x;
        #pragma unroll
        for (int tt = 0; tt < 4; tt++) {
            mean[tt] = smp[tt] * (1.0f / DMODEL);
            float var = sqp[tt] * (1.0f / DMODEL) - mean[tt] * mean[tt];
            rstd[tt] = rsqrtf(var + LN_EPS);
        }
    }
    __syncthreads();
    #pragma unroll
    for (int i = 0; i < 3; i++) {
        int d = tid + i * 256;
        float g = ln1g[d], b = ln1b[d];
        #pragma unroll
        for (int tt = 0; tt < 4; tt++)
            sh[tt][d] = (sx[tt][d] - mean[tt]) * rstd[tt] * g + b;
    }
    __syncthreads();

    // v = LN1(x) @ Wv + bv (shared Wv loads across 4 tokens)
    {
        const int j = tid & 63, part = tid >> 6;
        float acc[4] = {0.f, 0.f, 0.f, 0.f};
        const int kbeg = part * 192;
        for (int k = kbeg; k < kbeg + 192; ++k) {
            float w = Wv[k * HDIM + j];
            #pragma unroll
            for (int tt = 0; tt < 4; tt++) acc[tt] += sh[tt][k] * w;
        }
        rs[tid] = make_float4(acc[0], acc[1], acc[2], acc[3]);
        __syncthreads();
        if (tid < 64) {
            float4 a = rs[tid], b = rs[tid + 64], c = rs[tid + 128], d = rs[tid + 192];
            float bvv = bv[tid];
            sv[0][tid] = a.x + b.x + c.x + d.x + bvv;
            sv[1][tid] = a.y + b.y + c.y + d.y + bvv;
            sv[2][tid] = a.z + b.z + c.z + d.z + bvv;
            sv[3][tid] = a.w + b.w + c.w + d.w + bvv;
        }
        __syncthreads();
    }

    // x1 = x + tile(v); LN2 stats
    #pragma unroll
    for (int tt = 0; tt < 4; tt++) { s[tt] = 0.f; q[tt] = 0.f; }
    #pragma unroll
    for (int i = 0; i < 3; i++) {
        int d = tid + i * 256;
        #pragma unroll
        for (int tt = 0; tt < 4; tt++) {
            float v1 = sx[tt][d] + sv[tt][d & 63];
            out[(size_t)(t0 + tt) * DMODEL + d] = v1;
            sx[tt][d] = v1;
            s[tt] += v1; q[tt] += v1 * v1;
        }
    }
    rs[tid] = make_float4(s[0], s[1], s[2], s[3]);
    rq[tid] = make_float4(q[0], q[1], q[2], q[3]);
    __syncthreads();
    for (int o = 128; o > 0; o >>= 1) {
        if (tid < o) {
            float4 a = rs[tid], b = rs[tid + o];
            rs[tid] = make_float4(a.x + b.x, a.y + b.y, a.z + b.z, a.w + b.w);
            float4 c = rq[tid], d = rq[tid + o];
            rq[tid] = make_float4(c.x + d.x, c.y + d.y, c.z + d.z, c.w + d.w);
        }
        __syncthreads();
    }
    {
        float4 sm = rs[0], sq = rq[0];
        const float* smp = &sm.x; const float* sqp = &sq.x;
        #pragma unroll
        for (int tt = 0; tt < 4; tt++) {
            mean[tt] = smp[tt] * (1.0f / DMODEL);
            float var = sqp[tt] * (1.0f / DMODEL) - mean[tt] * mean[tt];
            rstd[tt] = rsqrtf(var + LN_EPS);
        }
    }
    __syncthreads();
    #pragma unroll
    for (int i = 0; i < 3; i++) {
        int d = tid + i * 256;
        float g = ln2g[d], b = ln2b[d];
        #pragma unroll
        for (int tt = 0; tt < 4; tt++) {
            float h2 = (sx[tt][d] - mean[tt]) * rstd[tt] * g + b;
            g_h2[(size_t)(t0 + tt) * DMODEL + d] = h2;
            sh[tt][d] = h2;
        }
    }
    __syncthreads();

    // gating logits + argmax
    {
        const int je = tid & 7, pe = tid >> 3;
        float acc[4] = {0.f, 0.f, 0.f, 0.f};
        const int kbeg = pe * 24;
        for (int k = kbeg; k < kbeg + 24; ++k) {
            float w = Wg[k * NEXP + je];
            #pragma unroll
            for (int tt = 0; tt < 4; tt++) acc[tt] += sh[tt][k] * w;
        }
        rs[tid] = make_float4(acc[0], acc[1], acc[2], acc[3]);
        __syncthreads();
        if (tid < NEXP) {
            float4 l = make_float4(0.f, 0.f, 0.f, 0.f);
            #pragma unroll
            for (int p = 0; p < 32; ++p) {
                float4 a = rs[p * 8 + tid];
                l.x += a.x; l.y += a.y; l.z += a.z; l.w += a.w;
            }
            float bgv = bg[tid];
            slog[0][tid] = l.x + bgv;
            slog[1][tid] = l.y + bgv;
            slog[2][tid] = l.z + bgv;
            slog[3][tid] = l.w + bgv;
        }
        __syncthreads();
        if (tid < 4) {
            int best = 0;
            float bvl = slog[tid][0];
            #pragma unroll
            for (int e = 1; e < NEXP; ++e)
                if (slog[tid][e] > bvl) { bvl = slog[tid][e]; best = e; }
            g_top1[t0 + tid] = best;
        }
    }
}

// ---------------- K2: route/compact ----------------
__global__ __launch_bounds__(512) void k_route()
{
    __shared__ int cnt[NEXP];
    __shared__ int base[NEXP];
    int tid = threadIdx.x;
    if (tid < NEXP) cnt[tid] = 0;
    __syncthreads();
    for (int t = tid; t < T_TOK; t += 512) atomicAdd(&cnt[g_top1[t]], 1);
    __syncthreads();
    if (tid == 0) {
        int s = 0;
        for (int e = 0; e < NEXP; ++e) { base[e] = s; g_off[e] = s; s += cnt[e]; }
        g_off[NEXP] = s;
    }
    __syncthreads();
    if (tid < NEXP) cnt[tid] = 0;
    __syncthreads();
    for (int t = tid; t < T_TOK; t += 512) {
        int e = g_top1[t];
        int pos = base[e] + atomicAdd(&cnt[e], 1);
        g_perm[pos] = t;
        g_inv[t] = pos;
    }
}

// ---------------- K3: mid = gelu(h2[perm] @ W1[e] + b1[e]) ----------------
__global__ __launch_bounds__(256, 2) void k_ffn1(
    const float* __restrict__ W1, const float* __restrict__ b1)
{
    const int e   = blockIdx.z;
    const int off = g_off[e];
    const int Me  = g_off[e + 1] - off;
    const int m0  = blockIdx.y * BM;
    if (m0 >= Me) return;
    const int n0  = blockIdx.x * BN;

    extern __shared__ char smem[];
    const uint32_t sb = smem_u32(smem);

    const int tid = threadIdx.x, lane = tid & 31, wid = tid >> 5;
    const int wm = (wid & 1) * 64, wn = (wid >> 1) * 32;

    const int arw = tid >> 1;
    const bool av = (m0 + arw) < Me;
    const float* arow = g_h2 + (size_t)(av ? g_perm[off + m0 + arw] : 0) * DMODEL;
    const int asz = av ? 16 : 0;
    const float* wblk = W1 + (size_t)e * DMODEL * FFDIM + n0;

    float C[4][4][4];
    #pragma unroll
    for (int i = 0; i < 4; i++)
        #pragma unroll
        for (int j = 0; j < 4; j++)
            #pragma unroll
            for (int qq = 0; qq < 4; qq++) C[i][j][qq] = 0.0f;

    stage_issue(sb,               arow,      asz, wblk,                      FFDIM, tid); CP_COMMIT();
    stage_issue(sb + STAGE_BYTES, arow + 32, asz, wblk + (size_t)32 * FFDIM, FFDIM, tid); CP_COMMIT();

    const int NK = DMODEL / BK;   // 24
    for (int it = 0; it < NK; ++it) {
        if (it + 2 < NK) cp_wait<1>(); else cp_wait<0>();
        __syncthreads();
        // stage(it+2) below writes buf (it+2)%3 == (it-1)%3; its last readers
        // (compute(it-1)) are fenced by the __syncthreads() above.
        uint32_t sc = sb + (uint32_t)(it % 3) * STAGE_BYTES;
        compute_stage(C, sc, sc + A_BYTES, wm, wn, lane);
        if (it + 2 < NK) {
            uint32_t s2 = sb + (uint32_t)((it + 2) % 3) * STAGE_BYTES;
            stage_issue(s2, arow + (it + 2) * 32, asz,
                        wblk + (size_t)(it + 2) * 32 * FFDIM, FFDIM, tid);
            CP_COMMIT();
        }
    }

    // epilogue: +b1, gelu, store
    const int grp = lane >> 2, tg = lane & 3;
    const float* bb = b1 + (size_t)e * FFDIM + n0;
    #pragma unroll
    for (int i = 0; i < 4; i++) {
        int r_lo = wm + i * 16 + grp;
        int r_hi = r_lo + 8;
        bool v_lo = (m0 + r_lo) < Me, v_hi = (m0 + r_hi) < Me;
        float* d_lo = g_mid + (size_t)(off + m0 + r_lo) * FFDIM + n0;
        float* d_hi = g_mid + (size_t)(off + m0 + r_hi) * FFDIM + n0;
        #pragma unroll
        for (int j = 0; j < 4; j++) {
            int nc = wn + j * 8 + tg * 2;
            float b0 = bb[nc], b1v = bb[nc + 1];
            if (v_lo) {
                float2 o = make_float2(gelu_f(C[i][j][0] + b0), gelu_f(C[i][j][1] + b1v));
                *(float2*)(d_lo + nc) = o;
            }
            if (v_hi) {
                float2 o = make_float2(gelu_f(C[i][j][2] + b0), gelu_f(C[i][j][3] + b1v));
                *(float2*)(d_hi + nc) = o;
            }
        }
    }
}

// ---------------- K4: part[spl] = mid @ W2[e][kslice]  (split-K=3) ----------------
__global__ __launch_bounds__(256, 2) void k_ffn2(const float* __restrict__ W2)
{
    const int z   = blockIdx.z;
    const int e   = z / NSPLIT;
    const int spl = z % NSPLIT;
    const int off = g_off[e];
    const int Me  = g_off[e + 1] - off;
    const int m0  = blockIdx.y * BM;
    if (m0 >= Me) return;
    const int n0  = blockIdx.x * BN;
    const int kbase = spl * (FFDIM / NSPLIT);   // 1024

    extern __shared__ char smem[];
    const uint32_t sb = smem_u32(smem);

    const int tid = threadIdx.x, lane = tid & 31, wid = tid >> 5;
    const int wm = (wid & 1) * 64, wn = (wid >> 1) * 32;

    const int arw = tid >> 1;
    const bool av = (m0 + arw) < Me;
    const float* arow = g_mid + (size_t)(off + (av ? m0 + arw : 0)) * FFDIM + kbase;
    const int asz = av ? 16 : 0;
    const float* wblk = W2 + (size_t)e * FFDIM * DMODEL + (size_t)kbase * DMODEL + n0;

    float C[4][4][4];
    #pragma unroll
    for (int i = 0; i < 4; i++)
        #pragma unroll
        for (int j = 0; j < 4; j++)
            #pragma unroll
            for (int qq = 0; qq < 4; qq++) C[i][j][qq] = 0.0f;

    stage_issue(sb,               arow,      asz, wblk,                       DMODEL, tid); CP_COMMIT();
    stage_issue(sb + STAGE_BYTES, arow + 32, asz, wblk + (size_t)32 * DMODEL, DMODEL, tid); CP_COMMIT();

    const int NK = (FFDIM / NSPLIT) / BK;   // 32
    for (int it = 0; it < NK; ++it) {
        if (it + 2 < NK) cp_wait<1>(); else cp_wait<0>();
        __syncthreads();
        uint32_t sc = sb + (uint32_t)(it % 3) * STAGE_BYTES;
        compute_stage(C, sc, sc + A_BYTES, wm, wn, lane);
        if (it + 2 < NK) {
            uint32_t s2 = sb + (uint32_t)((it + 2) % 3) * STAGE_BYTES;
            stage_issue(s2, arow + (it + 2) * 32, asz,
                        wblk + (size_t)(it + 2) * 32 * DMODEL, DMODEL, tid);
            CP_COMMIT();
        }
    }

    // epilogue: store partials (no bias here)
    const int grp = lane >> 2, tg = lane & 3;
    float* pbase = g_part + (size_t)spl * T_TOK * DMODEL;
    #pragma unroll
    for (int i = 0; i < 4; i++) {
        int r_lo = wm + i * 16 + grp;
        int r_hi = r_lo + 8;
        bool v_lo = (m0 + r_lo) < Me, v_hi = (m0 + r_hi) < Me;
        float* d_lo = pbase + (size_t)(off + m0 + r_lo) * DMODEL + n0;
        float* d_hi = pbase + (size_t)(off + m0 + r_hi) * DMODEL + n0;
        #pragma unroll
        for (int j = 0; j < 4; j++) {
            int nc = wn + j * 8 + tg * 2;
            if (v_lo) *(float2*)(d_lo + nc) = make_float2(C[i][j][0], C[i][j][1]);
            if (v_hi) *(float2*)(d_hi + nc) = make_float2(C[i][j][2], C[i][j][3]);
        }
    }
}

// ---------------- K5: out[t] += part0 + part1 + part2 + b2[e] ----------------
__global__ __launch_bounds__(192) void k_fin(const float* __restrict__ b2,
                                             float* __restrict__ out)
{
    const int t = blockIdx.x;
    const int c = threadIdx.x * 4;
    const int r = g_inv[t];
    const int e = g_top1[t];
    float4 p0 = *(const float4*)(g_part + (size_t)r * DMODEL + c);
    float4 p1 = *(const float4*)(g_part + ((size_t)T_TOK + r) * DMODEL + c);
    float4 p2 = *(const float4*)(g_part + ((size_t)2 * T_TOK + r) * DMODEL + c);
    float4 bb = *(const float4*)(b2 + (size_t)e * DMODEL + c);
    float4 o  = *(float4*)(out + (size_t)t * DMODEL + c);
    o.x += p0.x + p1.x + p2.x + bb.x;
    o.y += p0.y + p1.y + p2.y + bb.y;
    o.z += p0.z + p1.z + p2.z + bb.z;
    o.w += p0.w + p1.w + p2.w + bb.w;
    *(float4*)(out + (size_t)t * DMODEL + c) = o;
}

// ---------------- launch ----------------
extern "C" void kernel_launch(void* const* d_in, const int* in_sizes, int n_in,
                              void* d_out, int out_size)
{
    (void)in_sizes; (void)n_in; (void)out_size;
    const float* x    = (const float*)d_in[0];
    const float* ln1g = (const float*)d_in[1];
    const float* ln1b = (const float*)d_in[2];
    // d_in[3..6] = Wq,bq,Wk,bk : analytically cancelled
    const float* Wv   = (const float*)d_in[7];
    const float* bv   = (const float*)d_in[8];
    const float* ln2g = (const float*)d_in[9];
    const float* ln2b = (const float*)d_in[10];
    const float* Wg   = (const float*)d_in[11];
    const float* bg   = (const float*)d_in[12];
    const float* W1   = (const float*)d_in[13];
    const float* b1   = (const float*)d_in[14];
    const float* W2   = (const float*)d_in[15];
    const float* b2   = (const float*)d_in[16];
    float* out = (float*)d_out;

    static bool attr_done = false;
    if (!attr_done) {
        cudaFuncSetAttribute(k_ffn1, cudaFuncAttributeMaxDynamicSharedMemorySize, SMEM_TOT);
        cudaFuncSetAttribute(k_ffn2, cudaFuncAttributeMaxDynamicSharedMemorySize, SMEM_TOT);
        attr_done = true;
    }

    k_pre<<<T_TOK / 4, 256>>>(x, ln1g, ln1b, Wv, bv, ln2g, ln2b, Wg, bg, out);
    k_route<<<1, 512>>>();
    k_ffn1<<<dim3(FFDIM / BN, MT128, NEXP), 256, SMEM_TOT>>>(W1, b1);
    k_ffn2<<<dim3(DMODEL / BN, MT128, NEXP * NSPLIT), 256, SMEM_TOT>>>(W2);
    k_fin<<<T_TOK, 192>>>(b2, out);
}